// round 16
// baseline (speedup 1.0000x reference)
#include <cuda_runtime.h>
#include <cstdint>

#define BB   32
#define TT   128
#define KD   32
#define HH   4
#define DINP 160
#define HIDN 256

// Scratch (static device global; no allocation).
__device__ float g_act[BB * TT * DINP];     // [x | state]  4096 x 160

typedef unsigned long long ull;

__device__ __forceinline__ ull ffma2(ull a, ull b, ull c) {
    ull d;
    asm("fma.rn.f32x2 %0, %1, %2, %3;" : "=l"(d) : "l"(a), "l"(b), "l"(c));
    return d;
}
__device__ __forceinline__ ull pack2(float x, float y) {
    ull r;
    asm("mov.b64 %0, {%1, %2};" : "=l"(r) : "f"(x), "f"(y));
    return r;
}
__device__ __forceinline__ float2 unpack2(ull v) {
    float x, y;
    asm("mov.b64 {%0, %1}, %2;" : "=f"(x), "=f"(y) : "l"(v));
    return make_float2(x, y);
}

// ---------------------------------------------------------------------------
// Fused attention smem layout (floats). P aliases the proj staging region.
// ---------------------------------------------------------------------------
#define OFF_ST    0            // stateT [32][pitch 132]       4224
#define OFF_WQ    4224         // WqT-slice [32][pitch 68]     2176
#define OFF_WKV   6400         // Wk|Wv slice [32][pitch 68]   2176  (end 8576)
#define OFF_P     0            // P [128][64]                  8192  (alias)
#define OFF_KT    8576         // kT [32][128]                 4096
#define OFF_VT    12672        // vT [32][128]                 4096
#define OFF_QT    16768        // qT [32][64]                  2048
#define OFF_MX    18816        // [4][64]
#define OFF_SM    19072        // [4][64]
#define OFF_INV   19328        // [64]
#define ATTN_SMEM_FLOATS 19392
#define ATTN_SMEM_BYTES  (ATTN_SMEM_FLOATS * 4)

// ---------------------------------------------------------------------------
// Kernel 1 (fused QKV-proj + masked attention), 64 query rows of one (b,h).
// grid 256 = (b, h, ihalf), 256 threads, 2 CTA/SM.  (byte-identical to R8/R15)
// ---------------------------------------------------------------------------
__global__ void __launch_bounds__(256, 2) attn_kernel(
    const float* __restrict__ state,
    const float* __restrict__ Wq,
    const float* __restrict__ Wk,
    const float* __restrict__ Wv)
{
    extern __shared__ float sm[];
    const int bx = blockIdx.x;
    const int b = bx >> 3, h = (bx >> 1) & 3, ihalf = bx & 1;
    const int t = threadIdx.x;
    const int ig0 = ihalf * 64;

    float* sT    = sm + OFF_ST;
    float* swq   = sm + OFF_WQ;
    float* swkv  = sm + OFF_WKV;
    float* P     = sm + OFF_P;
    float* kT    = sm + OFF_KT;
    float* vT    = sm + OFF_VT;
    float* qT    = sm + OFF_QT;
    float* s_mx  = sm + OFF_MX;
    float* s_sm  = sm + OFF_SM;
    float* s_inv = sm + OFF_INV;

    // ---- stage stateT [c][j] (pitch 132) and weight slices (pitch 68)
    {
        int r = t >> 1, c0 = (t & 1) * 16;
        const float4* p = (const float4*)(state + ((size_t)b * TT + r) * KD + c0);
        #pragma unroll
        for (int w = 0; w < 4; w++) {
            float4 v = p[w];
            sT[(c0 + 4 * w + 0) * 132 + r] = v.x;
            sT[(c0 + 4 * w + 1) * 132 + r] = v.y;
            sT[(c0 + 4 * w + 2) * 132 + r] = v.z;
            sT[(c0 + 4 * w + 3) * 132 + r] = v.w;
        }
    }
    {
        int r = t >> 3, q = t & 7;      // 32 rows x 8 float4-chunks of the 32-col slice
        size_t src = (size_t)r * (KD * HH) + h * KD + q * 4;
        *(float4*)&swq[r * 68 + q * 4]        = *(const float4*)(Wq + src);
        *(float4*)&swkv[r * 68 + q * 4]       = *(const float4*)(Wk + src);
        *(float4*)&swkv[r * 68 + 32 + q * 4]  = *(const float4*)(Wv + src);
    }
    __syncthreads();

    // ---- KV projection: 128 rows x 64 cols (K|V), tile 8r x 4c per thread
    {
        const int rg = t & 15, cg = t >> 4;
        const int j0 = rg * 8, c0 = cg * 4;
        ull acc[8][2];
        #pragma unroll
        for (int r = 0; r < 8; r++) { acc[r][0] = 0ull; acc[r][1] = 0ull; }

        #pragma unroll 8
        for (int k = 0; k < KD; k++) {
            float4 a0 = *(const float4*)&sT[k * 132 + j0];
            float4 a1 = *(const float4*)&sT[k * 132 + j0 + 4];
            ulonglong2 b2 = *(const ulonglong2*)&swkv[k * 68 + c0];
            ull ad;
            ad = pack2(a0.x, a0.x); acc[0][0] = ffma2(ad, b2.x, acc[0][0]); acc[0][1] = ffma2(ad, b2.y, acc[0][1]);
            ad = pack2(a0.y, a0.y); acc[1][0] = ffma2(ad, b2.x, acc[1][0]); acc[1][1] = ffma2(ad, b2.y, acc[1][1]);
            ad = pack2(a0.z, a0.z); acc[2][0] = ffma2(ad, b2.x, acc[2][0]); acc[2][1] = ffma2(ad, b2.y, acc[2][1]);
            ad = pack2(a0.w, a0.w); acc[3][0] = ffma2(ad, b2.x, acc[3][0]); acc[3][1] = ffma2(ad, b2.y, acc[3][1]);
            ad = pack2(a1.x, a1.x); acc[4][0] = ffma2(ad, b2.x, acc[4][0]); acc[4][1] = ffma2(ad, b2.y, acc[4][1]);
            ad = pack2(a1.y, a1.y); acc[5][0] = ffma2(ad, b2.x, acc[5][0]); acc[5][1] = ffma2(ad, b2.y, acc[5][1]);
            ad = pack2(a1.z, a1.z); acc[6][0] = ffma2(ad, b2.x, acc[6][0]); acc[6][1] = ffma2(ad, b2.y, acc[6][1]);
            ad = pack2(a1.w, a1.w); acc[7][0] = ffma2(ad, b2.x, acc[7][0]); acc[7][1] = ffma2(ad, b2.y, acc[7][1]);
        }

        float cs[4][8];
        #pragma unroll
        for (int r = 0; r < 8; r++) {
            float2 e0 = unpack2(acc[r][0]), e1 = unpack2(acc[r][1]);
            cs[0][r] = e0.x; cs[1][r] = e0.y; cs[2][r] = e1.x; cs[3][r] = e1.y;
        }
        #pragma unroll
        for (int cc = 0; cc < 4; cc++) {
            int c = c0 + cc;
            float* dst = (c < KD) ? (kT + c * TT + j0) : (vT + (c - KD) * TT + j0);
            *(float4*)dst       = make_float4(cs[cc][0], cs[cc][1], cs[cc][2], cs[cc][3]);
            *(float4*)(dst + 4) = make_float4(cs[cc][4], cs[cc][5], cs[cc][6], cs[cc][7]);
        }
    }

    // ---- Q projection (threads 0-127); concat-tail copy (threads 128-255, h==0)
    if (t < 128) {
        const int rg = t & 15, cg = t >> 4;
        const int i0 = rg * 4, c0 = cg * 4;
        ull acc[4][2];
        #pragma unroll
        for (int r = 0; r < 4; r++) { acc[r][0] = 0ull; acc[r][1] = 0ull; }

        #pragma unroll 8
        for (int k = 0; k < KD; k++) {
            float4 a0 = *(const float4*)&sT[k * 132 + ig0 + i0];
            ulonglong2 b2 = *(const ulonglong2*)&swq[k * 68 + c0];
            ull ad;
            ad = pack2(a0.x, a0.x); acc[0][0] = ffma2(ad, b2.x, acc[0][0]); acc[0][1] = ffma2(ad, b2.y, acc[0][1]);
            ad = pack2(a0.y, a0.y); acc[1][0] = ffma2(ad, b2.x, acc[1][0]); acc[1][1] = ffma2(ad, b2.y, acc[1][1]);
            ad = pack2(a0.z, a0.z); acc[2][0] = ffma2(ad, b2.x, acc[2][0]); acc[2][1] = ffma2(ad, b2.y, acc[2][1]);
            ad = pack2(a0.w, a0.w); acc[3][0] = ffma2(ad, b2.x, acc[3][0]); acc[3][1] = ffma2(ad, b2.y, acc[3][1]);
        }
        float qs[4][4];
        #pragma unroll
        for (int r = 0; r < 4; r++) {
            float2 e0 = unpack2(acc[r][0]), e1 = unpack2(acc[r][1]);
            qs[0][r] = e0.x; qs[1][r] = e0.y; qs[2][r] = e1.x; qs[3][r] = e1.y;
        }
        #pragma unroll
        for (int cc = 0; cc < 4; cc++)
            *(float4*)&qT[(c0 + cc) * 64 + i0] =
                make_float4(qs[cc][0], qs[cc][1], qs[cc][2], qs[cc][3]);
    } else if (h == 0) {
        int n = t - 128;                           // 512 float4s, 4 per thread
        #pragma unroll
        for (int u = 0; u < 4; u++) {
            int m = n + u * 128;
            int row = m >> 3, c = (m & 7) * 4;
            size_t gr = (size_t)b * TT + ig0 + row;
            float4 v = *(const float4*)(state + gr * KD + c);
            *(float4*)(g_act + gr * DINP + 4 * KD + c) = v;
        }
    }
    __syncthreads();

    // ---- GEMM1: S^T[j][i] = K[j]·Q[i]; tile 8i x 4j (reads smem kT/qT)
    {
        const int ig = t >> 5, jg = t & 31;
        const int i0 = ig * 8, j0 = jg * 4;
        ull acc[4][4];
        #pragma unroll
        for (int c = 0; c < 4; c++)
            #pragma unroll
            for (int p = 0; p < 4; p++) acc[c][p] = 0ull;

        #pragma unroll 4
        for (int kk = 0; kk < KD; kk++) {
            const float* qrow = qT + kk * 64 + i0;
            ulonglong2 a01 = *(const ulonglong2*)qrow;
            ulonglong2 a23 = *(const ulonglong2*)(qrow + 4);
            float4 bj = *(const float4*)(kT + kk * TT + j0);
            ull bd;
            bd = pack2(bj.x, bj.x);
            acc[0][0] = ffma2(bd, a01.x, acc[0][0]); acc[0][1] = ffma2(bd, a01.y, acc[0][1]);
            acc[0][2] = ffma2(bd, a23.x, acc[0][2]); acc[0][3] = ffma2(bd, a23.y, acc[0][3]);
            bd = pack2(bj.y, bj.y);
            acc[1][0] = ffma2(bd, a01.x, acc[1][0]); acc[1][1] = ffma2(bd, a01.y, acc[1][1]);
            acc[1][2] = ffma2(bd, a23.x, acc[1][2]); acc[1][3] = ffma2(bd, a23.y, acc[1][3]);
            bd = pack2(bj.z, bj.z);
            acc[2][0] = ffma2(bd, a01.x, acc[2][0]); acc[2][1] = ffma2(bd, a01.y, acc[2][1]);
            acc[2][2] = ffma2(bd, a23.x, acc[2][2]); acc[2][3] = ffma2(bd, a23.y, acc[2][3]);
            bd = pack2(bj.w, bj.w);
            acc[3][0] = ffma2(bd, a01.x, acc[3][0]); acc[3][1] = ffma2(bd, a01.y, acc[3][1]);
            acc[3][2] = ffma2(bd, a23.x, acc[3][2]); acc[3][3] = ffma2(bd, a23.y, acc[3][3]);
        }

        __syncthreads();    // proj staging fully consumed before P overwrites it
        #pragma unroll
        for (int c = 0; c < 4; c++) {
            int jglob = j0 + c;
            int rd = jglob - ig0 - i0;          // diag position within my 8 i's
            if (rd >= 0 && rd < 8) {
                int p = rd >> 1, hi = rd & 1;
                float2 v = unpack2(acc[c][p]);
                if (hi) v.y = -1e30f; else v.x = -1e30f;
                acc[c][p] = pack2(v.x, v.y);
            }
            ull* dst = (ull*)&P[jglob * 64 + i0];
            dst[0] = acc[c][0]; dst[1] = acc[c][1];
            dst[2] = acc[c][2]; dst[3] = acc[c][3];
        }
    }
    __syncthreads();

    // ---- softmax (over j) on P, in place
    {
        const float scale = 0.17677669529663687f;   // 1/sqrt(32)
        const int i = t & 63, q = t >> 6;
        float mx = -1e30f;
        #pragma unroll 8
        for (int jj = 0; jj < 32; jj++)
            mx = fmaxf(mx, P[(q * 32 + jj) * 64 + i]);
        s_mx[q * 64 + i] = mx;
        __syncthreads();
        float m = fmaxf(fmaxf(s_mx[0 * 64 + i], s_mx[1 * 64 + i]),
                        fmaxf(s_mx[2 * 64 + i], s_mx[3 * 64 + i]));
        float sum = 0.f;
        #pragma unroll 8
        for (int jj = 0; jj < 32; jj++) {
            int idx = (q * 32 + jj) * 64 + i;
            float e = __expf((P[idx] - m) * scale);
            P[idx] = e;
            sum += e;
        }
        s_sm[q * 64 + i] = sum;
    }
    __syncthreads();
    if (t < 64)
        s_inv[t] = 1.f / (s_sm[0 * 64 + t] + s_sm[1 * 64 + t] +
                          s_sm[2 * 64 + t] + s_sm[3 * 64 + t]);
    __syncthreads();

    // ---- GEMM2: O[i][d] = sum_j P[j][i] * V[j][d]; tile 4i x 2d (smem vT)
    {
        const int ig = t & 15, dg = t >> 4;
        const int i0 = ig * 4, d0 = dg * 2;
        ull o[2][2];
        o[0][0] = 0ull; o[0][1] = 0ull; o[1][0] = 0ull; o[1][1] = 0ull;
        const float* v0p = vT + d0 * TT;
        const float* v1p = v0p + TT;

        for (int j = 0; j < TT; j += 4) {
            float4 v40 = *(const float4*)(v0p + j);
            float4 v41 = *(const float4*)(v1p + j);
            float va0[4] = {v40.x, v40.y, v40.z, v40.w};
            float va1[4] = {v41.x, v41.y, v41.z, v41.w};
            #pragma unroll
            for (int u = 0; u < 4; u++) {
                ulonglong2 a = *(const ulonglong2*)&P[(j + u) * 64 + i0];
                ull vd0 = pack2(va0[u], va0[u]);
                ull vd1 = pack2(va1[u], va1[u]);
                o[0][0] = ffma2(vd0, a.x, o[0][0]); o[0][1] = ffma2(vd0, a.y, o[0][1]);
                o[1][0] = ffma2(vd1, a.x, o[1][0]); o[1][1] = ffma2(vd1, a.y, o[1][1]);
            }
        }

        #pragma unroll
        for (int p = 0; p < 2; p++) {
            float2 e0 = unpack2(o[0][p]);
            float2 e1 = unpack2(o[1][p]);
            float r0[2] = {e0.x, e0.y};
            float r1[2] = {e1.x, e1.y};
            #pragma unroll
            for (int u = 0; u < 2; u++) {
                int il = i0 + p * 2 + u;
                int iglob = ig0 + il;
                float inv = s_inv[il];
                float out0 = r0[u] * inv - v0p[iglob];
                float out1 = r1[u] * inv - v1p[iglob];
                *(float2*)(g_act + ((size_t)b * TT + iglob) * DINP + h * KD + d0)
                    = make_float2(out0, out1);
            }
        }
    }
}

// ---------------------------------------------------------------------------
// Kernel 2 (fused MLP): 32 rows/block, grid 128 (single wave), 256 threads.
// Thread tile 16 rows x 2 cols (8 ROW-PAIRS packed into FFMA2 lanes).
// Warp w: col-group (w&3)*64 + lane*2, row-set (w>>2)*16.
// W in registers (LDG.64 double-buffered; per-CTA W redundancy = 2 -> 106MB
// L2, below the FMA floor). a-operands come PRE-PAIRED from smem ull arrays
// (s_ap1[k][rp], s_ap2[k][rp], pitch 18), so no per-FMA packs; only W is
// dup'd (16 packs/chunk). Zero in-loop barriers; FMA-pipe-bound.
// Dynamic smem: s_ap1 160*18*8 = 22.5KB + s_ap2 256*18*8 = 36KB = 58.5KB.
// ---------------------------------------------------------------------------
#define CKP   8
#define MROWS 32
#define NRP   (MROWS / 2)                     // 16 row-pairs
#define APITCH 18                             // ull pitch (even -> 16B align)
#define NCH1  (DINP / CKP)                    // 20
#define NCH2  (HIDN / CKP)                    // 32
#define MLP_SMEM_BYTES ((DINP * APITCH + HIDN * APITCH) * 8)

// one chunk: a pre-paired from smem (ull), W slice in regs (ull = 2 cols)
__device__ __forceinline__ void mlp_chunk2(
    const ull* ap, int pitch, int rp0, int kg0, const ull* wb, ull acc[8][2])
{
    #pragma unroll
    for (int k = 0; k < CKP; k++) {
        float2 w = unpack2(wb[k]);
        ull wd0 = pack2(w.x, w.x);
        ull wd1 = pack2(w.y, w.y);
        const ulonglong2* arow = (const ulonglong2*)(ap + (kg0 + k) * pitch + rp0);
        ulonglong2 a01 = arow[0];
        ulonglong2 a23 = arow[1];
        ulonglong2 a45 = arow[2];
        ulonglong2 a67 = arow[3];
        acc[0][0] = ffma2(a01.x, wd0, acc[0][0]); acc[0][1] = ffma2(a01.x, wd1, acc[0][1]);
        acc[1][0] = ffma2(a01.y, wd0, acc[1][0]); acc[1][1] = ffma2(a01.y, wd1, acc[1][1]);
        acc[2][0] = ffma2(a23.x, wd0, acc[2][0]); acc[2][1] = ffma2(a23.x, wd1, acc[2][1]);
        acc[3][0] = ffma2(a23.y, wd0, acc[3][0]); acc[3][1] = ffma2(a23.y, wd1, acc[3][1]);
        acc[4][0] = ffma2(a45.x, wd0, acc[4][0]); acc[4][1] = ffma2(a45.x, wd1, acc[4][1]);
        acc[5][0] = ffma2(a45.y, wd0, acc[5][0]); acc[5][1] = ffma2(a45.y, wd1, acc[5][1]);
        acc[6][0] = ffma2(a67.x, wd0, acc[6][0]); acc[6][1] = ffma2(a67.x, wd1, acc[6][1]);
        acc[7][0] = ffma2(a67.y, wd0, acc[7][0]); acc[7][1] = ffma2(a67.y, wd1, acc[7][1]);
    }
}

__device__ __forceinline__ void ldw2(ull* dst, const float* src)
{
    #pragma unroll
    for (int kk = 0; kk < CKP; kk++)
        dst[kk] = *(const ull*)(src + (size_t)kk * HIDN);
}

__global__ void __launch_bounds__(256, 1) mlp_kernel(
    const float* __restrict__ W1, const float* __restrict__ b1,
    const float* __restrict__ W2, const float* __restrict__ b2,
    const float* __restrict__ Wo, const float* __restrict__ bo,
    float* __restrict__ out)
{
    extern __shared__ ull smu[];
    ull* s_ap1 = smu;                          // [160][18] paired acts
    ull* s_ap2 = smu + DINP * APITCH;          // [256][18] paired h1
    __shared__ float s_red[MROWS][4];

    const int rbase = blockIdx.x * MROWS;
    const int t = threadIdx.x;
    const int wrp  = t >> 5;
    const int lane = t & 31;
    const int c0  = (wrp & 3) * 64 + lane * 2;   // my 2 cols
    const int rp0 = (wrp >> 2) * 8;              // my 8 row-pairs
    const int r0g = (wrp >> 2) * 16;             // my 16 rows

    // ---- stage: row-major tile into tmp (= s_ap2 region), then build s_ap1
    {
        float* tmp = (float*)s_ap2;
        const float4* src = (const float4*)(g_act + (size_t)rbase * DINP);
        #pragma unroll
        for (int n = t; n < MROWS * DINP / 4; n += 256)
            ((float4*)tmp)[n] = src[n];
        __syncthreads();
        #pragma unroll
        for (int idx = t; idx < DINP * NRP; idx += 256) {
            int k = idx >> 4, rp = idx & 15;
            s_ap1[k * APITCH + rp] =
                pack2(tmp[(2 * rp) * DINP + k], tmp[(2 * rp + 1) * DINP + k]);
        }
    }

    ull acc[8][2];
    {
        float2 bl = *(const float2*)(b1 + c0);
        #pragma unroll
        for (int rp = 0; rp < 8; rp++) {
            acc[rp][0] = pack2(bl.x, bl.x);
            acc[rp][1] = pack2(bl.y, bl.y);
        }
    }

    const float* w1p = W1 + c0;     // this thread's 2-col slice base
    const float* w2p = W2 + c0;

    ull bufA[CKP], bufB[CKP];
    ldw2(bufA, w1p);                // chunk 0
    __syncthreads();                // s_ap1 built

    // ---- phase 1: 20 chunks over W1 (x2 unrolled ping-pong)
    #pragma unroll 1
    for (int ch = 0; ch < NCH1; ch += 2) {
        ldw2(bufB, w1p + (size_t)(ch + 1) * CKP * HIDN);
        mlp_chunk2(s_ap1, APITCH, rp0, ch * CKP, bufA, acc);
        if (ch + 2 < NCH1) ldw2(bufA, w1p + (size_t)(ch + 2) * CKP * HIDN);
        else               ldw2(bufA, w2p);                  // W2 chunk 0
        mlp_chunk2(s_ap1, APITCH, rp0, (ch + 1) * CKP, bufB, acc);
    }

    // ---- phase boundary: relu(acc) IS the paired h1 word -> s_ap2[c][rp]
    #pragma unroll
    for (int rp = 0; rp < 8; rp++) {
        float2 v0 = unpack2(acc[rp][0]);
        float2 v1 = unpack2(acc[rp][1]);
        s_ap2[(c0 + 0) * APITCH + rp0 + rp] = pack2(fmaxf(v0.x, 0.f), fmaxf(v0.y, 0.f));
        s_ap2[(c0 + 1) * APITCH + rp0 + rp] = pack2(fmaxf(v1.x, 0.f), fmaxf(v1.y, 0.f));
    }
    {
        float2 bl = *(const float2*)(b2 + c0);
        #pragma unroll
        for (int rp = 0; rp < 8; rp++) {
            acc[rp][0] = pack2(bl.x, bl.x);
            acc[rp][1] = pack2(bl.y, bl.y);
        }
    }
    __syncthreads();

    // ---- phase 2: 32 chunks over W2 (x2 unrolled ping-pong)
    #pragma unroll 1
    for (int ch = 0; ch < NCH2; ch += 2) {
        ldw2(bufB, w2p + (size_t)(ch + 1) * CKP * HIDN);
        mlp_chunk2(s_ap2, APITCH, rp0, ch * CKP, bufA, acc);
        if (ch + 2 < NCH2) ldw2(bufA, w2p + (size_t)(ch + 2) * CKP * HIDN);
        mlp_chunk2(s_ap2, APITCH, rp0, (ch + 1) * CKP, bufB, acc);
    }

    // ---- relu + dot with my 2-col Wo slice; shfl over 32 lanes (64 cols),
    //      then combine the 4 col-warps via s_red.
    float2 wo = *(const float2*)(Wo + c0);
    float p[16];
    #pragma unroll
    for (int rp = 0; rp < 8; rp++) {
        float2 cv0 = unpack2(acc[rp][0]);    // (row 2rp, row 2rp+1) @ col c0
        float2 cv1 = unpack2(acc[rp][1]);    // @ col c0+1
        p[2 * rp + 0] = fmaf(fmaxf(cv0.x, 0.f), wo.x, fmaxf(cv1.x, 0.f) * wo.y);
        p[2 * rp + 1] = fmaf(fmaxf(cv0.y, 0.f), wo.x, fmaxf(cv1.y, 0.f) * wo.y);
    }
    #pragma unroll
    for (int off = 16; off; off >>= 1) {
        #pragma unroll
        for (int r = 0; r < 16; r++)
            p[r] += __shfl_down_sync(0xffffffffu, p[r], off);
    }
    if (lane == 0) {
        #pragma unroll
        for (int r = 0; r < 16; r++)
            s_red[r0g + r][wrp & 3] = p[r];
    }
    __syncthreads();
    if (t < MROWS)
        out[rbase + t] = s_red[t][0] + s_red[t][1] + s_red[t][2] + s_red[t][3] + bo[0];
}

// ---------------------------------------------------------------------------
extern "C" void kernel_launch(void* const* d_in, const int* in_sizes, int n_in,
                              void* d_out, int out_size)
{
    (void)in_sizes; (void)n_in; (void)out_size;
    const float* state = (const float*)d_in[0];
    const float* Wq    = (const float*)d_in[1];
    const float* Wk    = (const float*)d_in[2];
    const float* Wv    = (const float*)d_in[3];
    const float* W1    = (const float*)d_in[4];
    const float* b1    = (const float*)d_in[5];
    const float* W2    = (const float*)d_in[6];
    const float* b2    = (const float*)d_in[7];
    const float* Wo    = (const float*)d_in[8];
    const float* bo    = (const float*)d_in[9];
    float* out = (float*)d_out;

    cudaFuncSetAttribute(attn_kernel,
                         cudaFuncAttributeMaxDynamicSharedMemorySize,
                         ATTN_SMEM_BYTES);
    cudaFuncSetAttribute(mlp_kernel,
                         cudaFuncAttributeMaxDynamicSharedMemorySize,
                         MLP_SMEM_BYTES);
    attn_kernel<<<BB * HH * 2, 256, ATTN_SMEM_BYTES>>>(state, Wq, Wk, Wv);
    mlp_kernel<<<(BB * TT) / MROWS, 256, MLP_SMEM_BYTES>>>(W1, b1, W2, b2, Wo, bo, out);
}